// round 15
// baseline (speedup 1.0000x reference)
#include <cuda_runtime.h>
#include <cuda_bf16.h>
#include <math.h>
#include <stdint.h>

#define BS   4
#define T    2048
#define HID  512
#define NH   8
#define DH   64
#define QKVN ((2*NH+1)*DH)   // 1088
#define ROWS (BS*T)          // 8192

// ---- scratch ----
__device__ float g_v  [(size_t)ROWS * DH];
__device__ float g_mv [(size_t)ROWS * DH];
__device__ float g_rowsum[(size_t)BS * NH * T];
__device__ __nv_bfloat16 g_qh[(size_t)BS * NH * T * DH];
__device__ __nv_bfloat16 g_ql[(size_t)BS * NH * T * DH];
__device__ __nv_bfloat16 g_kh[(size_t)BS * NH * T * DH];
__device__ __nv_bfloat16 g_kl[(size_t)BS * NH * T * DH];
__device__ __nv_bfloat16 g_xh[(size_t)ROWS * HID];
__device__ __nv_bfloat16 g_xl[(size_t)ROWS * HID];
__device__ __nv_bfloat16 g_wh[(size_t)QKVN * HID];
__device__ __nv_bfloat16 g_wl[(size_t)QKVN * HID];
__device__ float g_probs_fallback[(size_t)BS * NH * T * T];
__device__ float g_out_fallback[(size_t)ROWS * HID];

// ---- packed f32x2 helpers ----
__device__ __forceinline__ unsigned long long f32x2_fma(
    unsigned long long a, unsigned long long b, unsigned long long c) {
    unsigned long long d;
    asm("fma.rn.f32x2 %0, %1, %2, %3;" : "=l"(d) : "l"(a), "l"(b), "l"(c));
    return d;
}
__device__ __forceinline__ unsigned long long pack2(float lo, float hi) {
    unsigned long long r;
    asm("mov.b64 %0, {%1, %2};" : "=l"(r) : "f"(lo), "f"(hi));
    return r;
}
__device__ __forceinline__ float2 unpack2(unsigned long long v) {
    float2 r;
    asm("mov.b64 {%0, %1}, %2;" : "=f"(r.x), "=f"(r.y) : "l"(v));
    return r;
}

// ---- warp mma bf16 m16n8k16, fp32 accum ----
__device__ __forceinline__ void mma16816(
    float& c0, float& c1, float& c2, float& c3,
    uint32_t a0, uint32_t a1, uint32_t a2, uint32_t a3,
    uint32_t b0, uint32_t b1)
{
    asm volatile(
        "mma.sync.aligned.m16n8k16.row.col.f32.bf16.bf16.f32 "
        "{%0,%1,%2,%3}, {%4,%5,%6,%7}, {%8,%9}, {%0,%1,%2,%3};"
        : "+f"(c0), "+f"(c1), "+f"(c2), "+f"(c3)
        : "r"(a0), "r"(a1), "r"(a2), "r"(a3), "r"(b0), "r"(b1));
}

__device__ __forceinline__ void ldsm_x4(
    uint32_t& r0, uint32_t& r1, uint32_t& r2, uint32_t& r3, uint32_t addr)
{
    asm volatile("ldmatrix.sync.aligned.m8n8.x4.shared.b16 {%0,%1,%2,%3}, [%4];"
                 : "=r"(r0), "=r"(r1), "=r"(r2), "=r"(r3) : "r"(addr));
}
__device__ __forceinline__ uint32_t smem_addr_u32(const void* p) {
    return (uint32_t)__cvta_generic_to_shared(p);
}

__device__ __forceinline__ uint32_t bf2pair(float a, float b) {
    __nv_bfloat162 p;
    p.x = __float2bfloat16_rn(a);
    p.y = __float2bfloat16_rn(b);
    return *reinterpret_cast<uint32_t*>(&p);
}

// ============================================================
// Small fp32 GEMM (out = mv @ w_out, K=64).
// ============================================================
__global__ __launch_bounds__(256) void gemm64x2(
    const float* __restrict__ A, const float* __restrict__ B, float* __restrict__ C,
    int K, int lda, int ldb, int ldc)
{
    __shared__ float As[16][68];
    __shared__ float Bs[16][64];
    const int tid = threadIdx.x;
    const int tx = tid & 15, ty = tid >> 4;
    const int rowbase = blockIdx.y * 64;
    const int colbase = blockIdx.x * 64;
    unsigned long long acc[4][2] = {};
    for (int k0 = 0; k0 < K; k0 += 16) {
        {
            int m = tid >> 2, k = (tid & 3) * 4;
            float4 v = *reinterpret_cast<const float4*>(A + (size_t)(rowbase + m) * lda + k0 + k);
            As[k + 0][m] = v.x; As[k + 1][m] = v.y; As[k + 2][m] = v.z; As[k + 3][m] = v.w;
        }
        {
            int k = tid >> 4, n = (tid & 15) * 4;
            *reinterpret_cast<float4*>(&Bs[k][n]) =
                *reinterpret_cast<const float4*>(B + (size_t)(k0 + k) * ldb + colbase + n);
        }
        __syncthreads();
        #pragma unroll
        for (int kk = 0; kk < 16; kk++) {
            float4 a4 = *reinterpret_cast<const float4*>(&As[kk][ty * 4]);
            ulonglong2 b2 = *reinterpret_cast<const ulonglong2*>(&Bs[kk][tx * 4]);
            unsigned long long a0 = pack2(a4.x, a4.x), a1 = pack2(a4.y, a4.y);
            unsigned long long a2 = pack2(a4.z, a4.z), a3 = pack2(a4.w, a4.w);
            acc[0][0] = f32x2_fma(a0, b2.x, acc[0][0]); acc[0][1] = f32x2_fma(a0, b2.y, acc[0][1]);
            acc[1][0] = f32x2_fma(a1, b2.x, acc[1][0]); acc[1][1] = f32x2_fma(a1, b2.y, acc[1][1]);
            acc[2][0] = f32x2_fma(a2, b2.x, acc[2][0]); acc[2][1] = f32x2_fma(a2, b2.y, acc[2][1]);
            acc[3][0] = f32x2_fma(a3, b2.x, acc[3][0]); acc[3][1] = f32x2_fma(a3, b2.y, acc[3][1]);
        }
        __syncthreads();
    }
    #pragma unroll
    for (int i = 0; i < 4; i++) {
        float2 p0 = unpack2(acc[i][0]), p1 = unpack2(acc[i][1]);
        *reinterpret_cast<float4*>(C + (size_t)(rowbase + ty * 4 + i) * ldc + colbase + tx * 4) =
            make_float4(p0.x, p0.y, p1.x, p1.y);
    }
}

// ============================================================
// Fused prep: zero mv+rowsum, hi/lo split of x, transpose+split w.
// ============================================================
#define PREP_ZMV   512
#define PREP_ZRS   (PREP_ZMV + 64)
#define PREP_X     (PREP_ZRS + 4096)
#define PREP_W     (PREP_X + 136)

__global__ __launch_bounds__(256) void prep_kernel(
    const float* __restrict__ X, const float* __restrict__ W,
    float* __restrict__ mv, float* __restrict__ rowsum,
    __nv_bfloat16* __restrict__ Xh, __nv_bfloat16* __restrict__ Xl,
    __nv_bfloat16* __restrict__ Wh, __nv_bfloat16* __restrict__ Wl)
{
    __shared__ float s[64][65];
    const int blk = blockIdx.x;
    const int tid = threadIdx.x;

    if (blk < PREP_ZMV) {
        reinterpret_cast<float4*>(mv)[blk * 256 + tid] = make_float4(0.f, 0.f, 0.f, 0.f);
    } else if (blk < PREP_ZRS) {
        reinterpret_cast<float4*>(rowsum)[(blk - PREP_ZMV) * 256 + tid] =
            make_float4(0.f, 0.f, 0.f, 0.f);
    } else if (blk < PREP_X) {
        int idx = (blk - PREP_ZRS) * 256 + tid;
        float4 v = reinterpret_cast<const float4*>(X)[idx];
        size_t o = (size_t)idx * 4;
        __nv_bfloat16 h0 = __float2bfloat16_rn(v.x), h1 = __float2bfloat16_rn(v.y);
        __nv_bfloat16 h2 = __float2bfloat16_rn(v.z), h3 = __float2bfloat16_rn(v.w);
        Xh[o+0]=h0; Xh[o+1]=h1; Xh[o+2]=h2; Xh[o+3]=h3;
        Xl[o+0]=__float2bfloat16_rn(v.x - __bfloat162float(h0));
        Xl[o+1]=__float2bfloat16_rn(v.y - __bfloat162float(h1));
        Xl[o+2]=__float2bfloat16_rn(v.z - __bfloat162float(h2));
        Xl[o+3]=__float2bfloat16_rn(v.w - __bfloat162float(h3));
    } else {
        int tile = blk - PREP_X;
        int n0 = (tile % 17) * 64, k0 = (tile / 17) * 64;
        #pragma unroll
        for (int e = tid; e < 64 * 64; e += 256) {
            int r = e >> 6, c = e & 63;
            s[r][c] = W[(size_t)(k0 + r) * QKVN + n0 + c];
        }
        __syncthreads();
        #pragma unroll
        for (int e = tid; e < 64 * 64; e += 256) {
            int r = e >> 6, c = e & 63;
            float v = s[c][r];
            __nv_bfloat16 h = __float2bfloat16_rn(v);
            Wh[(size_t)(n0 + r) * HID + k0 + c] = h;
            Wl[(size_t)(n0 + r) * HID + k0 + c] = __float2bfloat16_rn(v - __bfloat162float(h));
        }
    }
}

// ============================================================
// qkv GEMM on HMMA; epilogue writes Q,K directly as bf16 hi/lo
// in [b][h][t][d] layout, V as fp32 into g_v.
// ============================================================
#define GB_STRIDE 40

__global__ __launch_bounds__(256) void gemm_bf16_kernel(
    const __nv_bfloat16* __restrict__ Ah, const __nv_bfloat16* __restrict__ Al,
    const __nv_bfloat16* __restrict__ BhT, const __nv_bfloat16* __restrict__ BlT,
    __nv_bfloat16* __restrict__ Qh, __nv_bfloat16* __restrict__ Ql,
    __nv_bfloat16* __restrict__ Kh, __nv_bfloat16* __restrict__ Kl,
    float* __restrict__ V)
{
    __shared__ __nv_bfloat16 sAh[128][GB_STRIDE];
    __shared__ __nv_bfloat16 sAl[128][GB_STRIDE];
    __shared__ __nv_bfloat16 sBh[64][GB_STRIDE];
    __shared__ __nv_bfloat16 sBl[64][GB_STRIDE];

    const int tid = threadIdx.x;
    const int wid = tid >> 5, lane = tid & 31;
    const int rowbase = blockIdx.y * 128;
    const int colbase = blockIdx.x * 64;
    const int mbase = (wid & 3) * 32, nbase = (wid >> 2) * 32;
    const int lr = lane >> 2, lk = (lane & 3) * 2;

    float acc[2][4][4];
    #pragma unroll
    for (int i = 0; i < 2; i++)
        #pragma unroll
        for (int j = 0; j < 4; j++)
            #pragma unroll
            for (int t = 0; t < 4; t++) acc[i][j][t] = 0.f;

    for (int k0 = 0; k0 < HID; k0 += 32) {
        #pragma unroll
        for (int e = tid; e < 512; e += 256) {
            int r = e >> 2, c = (e & 3) * 8;
            *(uint4*)(&sAh[r][c]) = *(const uint4*)(Ah + (size_t)(rowbase + r) * HID + k0 + c);
            *(uint4*)(&sAl[r][c]) = *(const uint4*)(Al + (size_t)(rowbase + r) * HID + k0 + c);
        }
        {
            int r = tid >> 2, c = (tid & 3) * 8;
            *(uint4*)(&sBh[r][c]) = *(const uint4*)(BhT + (size_t)(colbase + r) * HID + k0 + c);
            *(uint4*)(&sBl[r][c]) = *(const uint4*)(BlT + (size_t)(colbase + r) * HID + k0 + c);
        }
        __syncthreads();
        #pragma unroll
        for (int ks = 0; ks < 2; ks++) {
            const int kb = ks * 16 + lk;
            uint32_t ah[2][4], al[2][4];
            #pragma unroll
            for (int i = 0; i < 2; i++) {
                int r0 = mbase + i * 16 + lr;
                ah[i][0] = *(const uint32_t*)(&sAh[r0][kb]);
                ah[i][1] = *(const uint32_t*)(&sAh[r0 + 8][kb]);
                ah[i][2] = *(const uint32_t*)(&sAh[r0][kb + 8]);
                ah[i][3] = *(const uint32_t*)(&sAh[r0 + 8][kb + 8]);
                al[i][0] = *(const uint32_t*)(&sAl[r0][kb]);
                al[i][1] = *(const uint32_t*)(&sAl[r0 + 8][kb]);
                al[i][2] = *(const uint32_t*)(&sAl[r0][kb + 8]);
                al[i][3] = *(const uint32_t*)(&sAl[r0 + 8][kb + 8]);
            }
            #pragma unroll
            for (int j = 0; j < 4; j++) {
                int n = nbase + j * 8 + lr;
                uint32_t bh0 = *(const uint32_t*)(&sBh[n][kb]);
                uint32_t bh1 = *(const uint32_t*)(&sBh[n][kb + 8]);
                uint32_t bl0 = *(const uint32_t*)(&sBl[n][kb]);
                uint32_t bl1 = *(const uint32_t*)(&sBl[n][kb + 8]);
                #pragma unroll
                for (int i = 0; i < 2; i++) {
                    mma16816(acc[i][j][0], acc[i][j][1], acc[i][j][2], acc[i][j][3],
                             ah[i][0], ah[i][1], ah[i][2], ah[i][3], bh0, bh1);
                    mma16816(acc[i][j][0], acc[i][j][1], acc[i][j][2], acc[i][j][3],
                             ah[i][0], ah[i][1], ah[i][2], ah[i][3], bl0, bl1);
                    mma16816(acc[i][j][0], acc[i][j][1], acc[i][j][2], acc[i][j][3],
                             al[i][0], al[i][1], al[i][2], al[i][3], bh0, bh1);
                }
            }
        }
        __syncthreads();
    }

    #pragma unroll
    for (int i = 0; i < 2; i++) {
        int r = rowbase + mbase + i * 16 + lr;
        int b = r >> 11, t = r & (T - 1);
        #pragma unroll
        for (int j = 0; j < 4; j++) {
            int col = colbase + nbase + j * 8 + lk;
            float v0 = acc[i][j][0], v1 = acc[i][j][1];
            float v2 = acc[i][j][2], v3 = acc[i][j][3];
            if (col < 1024) {
                int hh = (col >> 6) & 7;
                int d  = col & 63;
                __nv_bfloat16* oh = (col >= 512) ? Kh : Qh;
                __nv_bfloat16* ol = (col >= 512) ? Kl : Ql;
                size_t dst  = ((size_t)(b * NH + hh) * T + t) * DH + d;
                size_t dst8 = dst + 8 * DH;
                uint32_t h01 = bf2pair(v0, v1);
                uint32_t h23 = bf2pair(v2, v3);
                __nv_bfloat162 hp0 = *reinterpret_cast<__nv_bfloat162*>(&h01);
                __nv_bfloat162 hp2 = *reinterpret_cast<__nv_bfloat162*>(&h23);
                uint32_t l01 = bf2pair(v0 - __bfloat162float(hp0.x),
                                       v1 - __bfloat162float(hp0.y));
                uint32_t l23 = bf2pair(v2 - __bfloat162float(hp2.x),
                                       v3 - __bfloat162float(hp2.y));
                *reinterpret_cast<uint32_t*>(oh + dst)  = h01;
                *reinterpret_cast<uint32_t*>(ol + dst)  = l01;
                *reinterpret_cast<uint32_t*>(oh + dst8) = h23;
                *reinterpret_cast<uint32_t*>(ol + dst8) = l23;
            } else {
                int d = col - 1024;
                size_t dst = ((size_t)b * T + t) * DH + d;
                *reinterpret_cast<float2*>(V + dst)          = make_float2(v0, v1);
                *reinterpret_cast<float2*>(V + dst + 8 * DH) = make_float2(v2, v3);
            }
        }
    }
}

// ============================================================
// Scores: ONE pass. MMA + exp + store unnormalized exp-P +
// rowsum atomics. Upper-tri blocks zero-fill. Diag masked.
// ============================================================
#define SC_STRIDE 72
#define SC_SMEM   (4 * 128 * SC_STRIDE * 2)

__device__ __forceinline__ void scores_load_tiles(
    const __nv_bfloat16* __restrict__ Qh, const __nv_bfloat16* __restrict__ Ql,
    const __nv_bfloat16* __restrict__ Kh, const __nv_bfloat16* __restrict__ Kl,
    int ki, int qi, int bh, __nv_bfloat16* smem)
{
    __nv_bfloat16* sQh = smem;
    __nv_bfloat16* sQl = smem + 128 * SC_STRIDE;
    __nv_bfloat16* sKh = smem + 2 * 128 * SC_STRIDE;
    __nv_bfloat16* sKl = smem + 3 * 128 * SC_STRIDE;
    const int tid = threadIdx.x;
    const size_t qoff = ((size_t)bh * T + qi * 128) * DH;
    const size_t koff = ((size_t)bh * T + ki * 128) * DH;
    #pragma unroll
    for (int e = tid; e < 1024; e += 256) {
        int r = e >> 3, c = (e & 7) * 8;
        *(uint4*)(sQh + r * SC_STRIDE + c) = *(const uint4*)(Qh + qoff + r * DH + c);
        *(uint4*)(sQl + r * SC_STRIDE + c) = *(const uint4*)(Ql + qoff + r * DH + c);
        *(uint4*)(sKh + r * SC_STRIDE + c) = *(const uint4*)(Kh + koff + r * DH + c);
        *(uint4*)(sKl + r * SC_STRIDE + c) = *(const uint4*)(Kl + koff + r * DH + c);
    }
    __syncthreads();
}

__device__ __forceinline__ void scores_half_mma(
    const __nv_bfloat16* smem, int c2, float acc[2][4][4])
{
    const __nv_bfloat16* sQh = smem;
    const __nv_bfloat16* sQl = smem + 128 * SC_STRIDE;
    const __nv_bfloat16* sKh = smem + 2 * 128 * SC_STRIDE;
    const __nv_bfloat16* sKl = smem + 3 * 128 * SC_STRIDE;

    const int tid = threadIdx.x;
    const int wid = tid >> 5, lane = tid & 31;
    const int wr = wid & 3, wc = wid >> 2;

    const int a_row = lane & 15;
    const int a_col = (lane >> 4) << 3;
    const int b_row = ((lane >> 4) << 3) + (lane & 7);
    const int b_col = ((lane >> 3) & 1) << 3;

    #pragma unroll
    for (int i = 0; i < 2; i++)
        #pragma unroll
        for (int j = 0; j < 4; j++)
            #pragma unroll
            for (int t = 0; t < 4; t++) acc[i][j][t] = 0.f;

    #pragma unroll
    for (int ks = 0; ks < 4; ks++) {
        const int kb0 = ks * 16;
        uint32_t ah[2][4], al[2][4];
        #pragma unroll
        for (int i = 0; i < 2; i++) {
            int r0 = wr * 32 + i * 16 + a_row;
            ldsm_x4(ah[i][0], ah[i][1], ah[i][2], ah[i][3],
                    smem_addr_u32(sQh + r0 * SC_STRIDE + kb0 + a_col));
            ldsm_x4(al[i][0], al[i][1], al[i][2], al[i][3],
                    smem_addr_u32(sQl + r0 * SC_STRIDE + kb0 + a_col));
        }
        #pragma unroll
        for (int jj = 0; jj < 2; jj++) {
            int n0 = wc * 64 + c2 * 32 + jj * 16 + b_row;
            uint32_t bh[4], bl[4];
            ldsm_x4(bh[0], bh[1], bh[2], bh[3],
                    smem_addr_u32(sKh + n0 * SC_STRIDE + kb0 + b_col));
            ldsm_x4(bl[0], bl[1], bl[2], bl[3],
                    smem_addr_u32(sKl + n0 * SC_STRIDE + kb0 + b_col));
            #pragma unroll
            for (int dj = 0; dj < 2; dj++) {
                int j = jj * 2 + dj;
                #pragma unroll
                for (int i = 0; i < 2; i++) {
                    mma16816(acc[i][j][0], acc[i][j][1], acc[i][j][2], acc[i][j][3],
                             ah[i][0], ah[i][1], ah[i][2], ah[i][3],
                             bh[2*dj], bh[2*dj+1]);
                    mma16816(acc[i][j][0], acc[i][j][1], acc[i][j][2], acc[i][j][3],
                             ah[i][0], ah[i][1], ah[i][2], ah[i][3],
                             bl[2*dj], bl[2*dj+1]);
                    mma16816(acc[i][j][0], acc[i][j][1], acc[i][j][2], acc[i][j][3],
                             al[i][0], al[i][1], al[i][2], al[i][3],
                             bh[2*dj], bh[2*dj+1]);
                }
            }
        }
    }
}

__global__ __launch_bounds__(256, 3) void scores_exp_kernel(
    const __nv_bfloat16* __restrict__ Qh, const __nv_bfloat16* __restrict__ Ql,
    const __nv_bfloat16* __restrict__ Kh, const __nv_bfloat16* __restrict__ Kl,
    float* __restrict__ rowsum, float* __restrict__ P)
{
    const int ki = blockIdx.x, qi = blockIdx.y, bh = blockIdx.z;
    const int tid = threadIdx.x;

    if (ki > qi) {
        const size_t base = ((size_t)bh * T + qi * 128) * T + ki * 128;
        const float4 z = make_float4(0.f, 0.f, 0.f, 0.f);
        #pragma unroll
        for (int e = tid; e < 4096; e += 256) {
            int r = e >> 5, c4 = (e & 31) * 4;
            *reinterpret_cast<float4*>(&P[base + (size_t)r * T + c4]) = z;
        }
        return;
    }
    const bool diag = (ki == qi);

    extern __shared__ __nv_bfloat16 smem[];
    scores_load_tiles(Qh, Ql, Kh, Kl, ki, qi, bh, smem);

    const int wid = tid >> 5, lane = tid & 31;
    const int wr = wid & 3, wc = wid >> 2;
    const int lr = lane >> 2, lk = (lane & 3) * 2;
    const float scale = 0.125f;

    float rs0a = 0.f, rs1a = 0.f, rs0b = 0.f, rs1b = 0.f;
    #pragma unroll
    for (int c2 = 0; c2 < 2; c2++) {
        float acc[2][4][4];
        scores_half_mma(smem, c2, acc);
        #pragma unroll
        for (int i = 0; i < 2; i++) {
            int qa = qi * 128 + wr * 32 + i * 16 + lr;
            int qb = qa + 8;
            float rs0 = 0.f, rs1 = 0.f;
            #pragma unroll
            for (int j = 0; j < 4; j++) {
                int col = ki * 128 + wc * 64 + c2 * 32 + j * 8 + lk;
                float2 va, vb;
                if (diag) {
                    va.x = (col     > qa) ? 0.f : __expf(acc[i][j][0] * scale);
                    va.y = (col + 1 > qa) ? 0.f : __expf(acc[i][j][1] * scale);
                    vb.x = (col     > qb) ? 0.f : __expf(acc[i][j][2] * scale);
                    vb.y = (col + 1 > qb) ? 0.f : __expf(acc[i][j][3] * scale);
                } else {
                    va.x = __expf(acc[i][j][0] * scale);
                    va.y = __expf(acc[i][j][1] * scale);
                    vb.x = __expf(acc[i][j][2] * scale);
                    vb.y = __expf(acc[i][j][3] * scale);
                }
                rs0 += va.x + va.y;
                rs1 += vb.x + vb.y;
                *reinterpret_cast<float2*>(&P[((size_t)bh * T + qa) * T + col]) = va;
                *reinterpret_cast<float2*>(&P[((size_t)bh * T + qb) * T + col]) = vb;
            }
            if (i == 0) { rs0a += rs0; rs1a += rs1; }
            else        { rs0b += rs0; rs1b += rs1; }
        }
    }
    #pragma unroll
    for (int o = 1; o <= 2; o <<= 1) {
        rs0a += __shfl_xor_sync(0xffffffffu, rs0a, o);
        rs1a += __shfl_xor_sync(0xffffffffu, rs1a, o);
        rs0b += __shfl_xor_sync(0xffffffffu, rs0b, o);
        rs1b += __shfl_xor_sync(0xffffffffu, rs1b, o);
    }
    if ((lane & 3) == 0) {
        int q0 = qi * 128 + wr * 32 + lr;
        atomicAdd(&rowsum[(size_t)bh * T + q0], rs0a);
        atomicAdd(&rowsum[(size_t)bh * T + q0 + 8], rs1a);
        atomicAdd(&rowsum[(size_t)bh * T + q0 + 16], rs0b);
        atomicAdd(&rowsum[(size_t)bh * T + q0 + 24], rs1b);
    }
}

// ============================================================
// Streaming normalize: P[bh, t, 0..t] *= 1/rowsum[bh, t].
// grid (2, T, BS*NH); block covers 1024 cols. Blocks fully above
// diagonal skip (those cols are already zero).
// ============================================================
__global__ __launch_bounds__(256) void normalize_kernel(
    float* __restrict__ P, const float* __restrict__ rowsum)
{
    const int t = blockIdx.y, bh = blockIdx.z;
    const int col = blockIdx.x * 1024 + threadIdx.x * 4;
    if (col > t) return;
    const float inv = 1.0f / rowsum[(size_t)bh * T + t];
    float4* p = reinterpret_cast<float4*>(P + ((size_t)bh * T + t) * T + col);
    float4 v = *p;
    v.x *= inv; v.y *= inv; v.z *= inv; v.w *= inv;   // zeros above diag stay zero
    *p = v;
}

// ============================================================
// mv += mean_h(P) @ V, flat-balanced: 132 blocks x exactly 4
// lower-tri tiles each, per batch. Flush acc on qt change.
// ============================================================
__device__ __forceinline__ void pv_flush(
    float* __restrict__ mv, int b, int qt,
    unsigned long long acc[4][2], int tx, int ty)
{
    #pragma unroll
    for (int i = 0; i < 4; i++) {
        float* dst = &mv[((size_t)b * T + qt * 64 + ty * 4 + i) * DH + tx * 4];
        float2 p0 = unpack2(acc[i][0]), p1 = unpack2(acc[i][1]);
        atomicAdd(dst + 0, p0.x);
        atomicAdd(dst + 1, p0.y);
        atomicAdd(dst + 2, p1.x);
        atomicAdd(dst + 3, p1.y);
    }
}

__global__ __launch_bounds__(256) void pv_flat_kernel(
    const float* __restrict__ P, const float* __restrict__ V,
    float* __restrict__ mv)
{
    const int g = blockIdx.x;       // 0..131
    const int b = blockIdx.y;

    __shared__ float Ps[64][65];
    __shared__ float Vs[64][64];

    const int tid = threadIdx.x;
    const int tx = tid & 15, ty = tid >> 4;
    const float* Vbase = V + (size_t)b * T * DH;

    // decode first tile index
    int idx = g * 4;
    int qt = (int)((sqrtf(8.0f * (float)idx + 1.0f) - 1.0f) * 0.5f);
    while ((qt + 1) * (qt + 2) / 2 <= idx) qt++;
    while (qt * (qt + 1) / 2 > idx) qt--;
    int kt = idx - qt * (qt + 1) / 2;

    unsigned long long acc[4][2] = {};
    bool dirty = false;

    #pragma unroll 1
    for (int it = 0; it < 4; it++) {
        #pragma unroll
        for (int e = tid; e < 64 * 16; e += 256) {
            int r = e >> 4, c4 = (e & 15) * 4;
            *reinterpret_cast<float4*>(&Vs[r][c4]) =
                *reinterpret_cast<const float4*>(Vbase + (size_t)(kt * 64 + r) * DH + c4);
            const size_t off = ((size_t)(qt * 64 + r)) * T + kt * 64 + c4;
            float4 sv = make_float4(0.f, 0.f, 0.f, 0.f);
            #pragma unroll
            for (int h = 0; h < NH; h++) {
                float4 v = *reinterpret_cast<const float4*>(
                    P + (size_t)(b * NH + h) * T * T + off);
                sv.x += v.x; sv.y += v.y; sv.z += v.z; sv.w += v.w;
            }
            Ps[r][c4 + 0] = sv.x * 0.125f; Ps[r][c4 + 1] = sv.y * 0.125f;
            Ps[r][c4 + 2] = sv.z * 0.125f; Ps[r][c4 + 3] = sv.w * 0.125f;
        }
        __syncthreads();

        #pragma unroll 16
        for (int kk = 0; kk < 64; kk++) {
            ulonglong2 b2 = *reinterpret_cast<const ulonglong2*>(&Vs[kk][tx * 4]);
            #pragma unroll
            for (int i = 0; i < 4; i++) {
                float a = Ps[ty * 4 + i][kk];
                unsigned long long a2 = pack2(a, a);
                acc[i][0] = f32x2_fma(a2, b2.x, acc[i][0]);
                acc[i][1] = f32x2_fma(a2, b2.y, acc[i][1]);
            }
        }
        __syncthreads();
        dirty = true;

        kt++;
        if (kt > qt) {           // row complete: flush and advance
            pv_flush(mv, b, qt, acc, tx, ty);
            #pragma unroll
            for (int i = 0; i < 4; i++) { acc[i][0] = 0ULL; acc[i][1] = 0ULL; }
            dirty = false;
            qt++;
            kt = 0;
        }
    }
    if (dirty)
        pv_flush(mv, b, qt, acc, tx, ty);
}

// ============================================================
extern "C" void kernel_launch(void* const* d_in, const int* in_sizes, int n_in,
                              void* d_out, int out_size)
{
    const float* x     = (const float*)d_in[0];
    const float* w_qkv = (const float*)d_in[1];
    const float* w_out = (const float*)d_in[2];

    const long OUT_E  = (long)ROWS * HID;
    const long PROB_E = (long)BS * NH * T * T;

    float *v_p, *mv_p, *rowsum_p, *probs_fb, *out_fb;
    __nv_bfloat16 *qh_p, *ql_p, *kh_p, *kl_p, *xh_p, *xl_p, *wh_p, *wl_p;
    cudaGetSymbolAddress((void**)&v_p,      g_v);
    cudaGetSymbolAddress((void**)&mv_p,     g_mv);
    cudaGetSymbolAddress((void**)&rowsum_p, g_rowsum);
    cudaGetSymbolAddress((void**)&qh_p,     g_qh);
    cudaGetSymbolAddress((void**)&ql_p,     g_ql);
    cudaGetSymbolAddress((void**)&kh_p,     g_kh);
    cudaGetSymbolAddress((void**)&kl_p,     g_kl);
    cudaGetSymbolAddress((void**)&xh_p,     g_xh);
    cudaGetSymbolAddress((void**)&xl_p,     g_xl);
    cudaGetSymbolAddress((void**)&wh_p,     g_wh);
    cudaGetSymbolAddress((void**)&wl_p,     g_wl);
    cudaGetSymbolAddress((void**)&probs_fb, g_probs_fallback);
    cudaGetSymbolAddress((void**)&out_fb,   g_out_fallback);

    float* out_ptr;
    float* probs_ptr;
    if ((long)out_size >= OUT_E + PROB_E) {
        out_ptr   = (float*)d_out;
        probs_ptr = (float*)d_out + OUT_E;
    } else if ((long)out_size == PROB_E) {
        out_ptr   = out_fb;
        probs_ptr = (float*)d_out;
    } else {
        out_ptr   = (float*)d_out;
        probs_ptr = probs_fb;
    }

    cudaFuncSetAttribute(scores_exp_kernel,
                         cudaFuncAttributeMaxDynamicSharedMemorySize, SC_SMEM);

    // 1) fused prep
    prep_kernel<<<PREP_W, 256>>>(x, w_qkv, mv_p, rowsum_p, xh_p, xl_p, wh_p, wl_p);

    // 2) qkv GEMM; epilogue emits Q,K bf16 hi/lo + V fp32
    gemm_bf16_kernel<<<dim3(QKVN / 64, ROWS / 128), 256>>>(
        xh_p, xl_p, wh_p, wl_p, qh_p, ql_p, kh_p, kl_p, v_p);

    // 3) single exp pass: unnormalized exp-P + rowsums + upper zero-fill
    scores_exp_kernel<<<dim3(T / 128, T / 128, BS * NH), 256, SC_SMEM>>>(
        qh_p, ql_p, kh_p, kl_p, rowsum_p, probs_ptr);

    // 4) streaming normalize (no MUFU)
    normalize_kernel<<<dim3(2, T, BS * NH), 256>>>(probs_ptr, rowsum_p);

    // 5) mv = mean_h(P) @ V (flat-balanced, 4 tiles per block)
    pv_flat_kernel<<<dim3(132, BS), 256>>>(probs_ptr, v_p, mv_p);

    // 6) out = mv @ w_out
    gemm64x2<<<dim3(HID / 64, ROWS / 64), 256>>>(mv_p, w_out, out_ptr, DH, DH, HID, HID);
}

// round 16
// speedup vs baseline: 1.0888x; 1.0888x over previous
#include <cuda_runtime.h>
#include <cuda_bf16.h>
#include <math.h>
#include <stdint.h>

#define BS   4
#define T    2048
#define HID  512
#define NH   8
#define DH   64
#define QKVN ((2*NH+1)*DH)   // 1088
#define ROWS (BS*T)          // 8192

// ---- scratch ----
__device__ float g_v  [(size_t)ROWS * DH];
__device__ float g_mv [(size_t)ROWS * DH];
__device__ float g_rowsum[(size_t)BS * NH * T];
__device__ __nv_bfloat16 g_qh[(size_t)BS * NH * T * DH];
__device__ __nv_bfloat16 g_ql[(size_t)BS * NH * T * DH];
__device__ __nv_bfloat16 g_kh[(size_t)BS * NH * T * DH];
__device__ __nv_bfloat16 g_kl[(size_t)BS * NH * T * DH];
__device__ __nv_bfloat16 g_xh[(size_t)ROWS * HID];
__device__ __nv_bfloat16 g_xl[(size_t)ROWS * HID];
__device__ __nv_bfloat16 g_wh[(size_t)QKVN * HID];
__device__ __nv_bfloat16 g_wl[(size_t)QKVN * HID];
__device__ float g_probs_fallback[(size_t)BS * NH * T * T];
__device__ float g_out_fallback[(size_t)ROWS * HID];

// ---- packed f32x2 helpers ----
__device__ __forceinline__ unsigned long long f32x2_fma(
    unsigned long long a, unsigned long long b, unsigned long long c) {
    unsigned long long d;
    asm("fma.rn.f32x2 %0, %1, %2, %3;" : "=l"(d) : "l"(a), "l"(b), "l"(c));
    return d;
}
__device__ __forceinline__ unsigned long long pack2(float lo, float hi) {
    unsigned long long r;
    asm("mov.b64 %0, {%1, %2};" : "=l"(r) : "f"(lo), "f"(hi));
    return r;
}
__device__ __forceinline__ float2 unpack2(unsigned long long v) {
    float2 r;
    asm("mov.b64 {%0, %1}, %2;" : "=f"(r.x), "=f"(r.y) : "l"(v));
    return r;
}

// ---- warp mma bf16 m16n8k16, fp32 accum ----
__device__ __forceinline__ void mma16816(
    float& c0, float& c1, float& c2, float& c3,
    uint32_t a0, uint32_t a1, uint32_t a2, uint32_t a3,
    uint32_t b0, uint32_t b1)
{
    asm volatile(
        "mma.sync.aligned.m16n8k16.row.col.f32.bf16.bf16.f32 "
        "{%0,%1,%2,%3}, {%4,%5,%6,%7}, {%8,%9}, {%0,%1,%2,%3};"
        : "+f"(c0), "+f"(c1), "+f"(c2), "+f"(c3)
        : "r"(a0), "r"(a1), "r"(a2), "r"(a3), "r"(b0), "r"(b1));
}

__device__ __forceinline__ void ldsm_x4(
    uint32_t& r0, uint32_t& r1, uint32_t& r2, uint32_t& r3, uint32_t addr)
{
    asm volatile("ldmatrix.sync.aligned.m8n8.x4.shared.b16 {%0,%1,%2,%3}, [%4];"
                 : "=r"(r0), "=r"(r1), "=r"(r2), "=r"(r3) : "r"(addr));
}
__device__ __forceinline__ uint32_t smem_addr_u32(const void* p) {
    return (uint32_t)__cvta_generic_to_shared(p);
}

__device__ __forceinline__ uint32_t bf2pair(float a, float b) {
    __nv_bfloat162 p;
    p.x = __float2bfloat16_rn(a);
    p.y = __float2bfloat16_rn(b);
    return *reinterpret_cast<uint32_t*>(&p);
}

// ============================================================
// Small fp32 GEMM (out = mv @ w_out, K=64).
// ============================================================
__global__ __launch_bounds__(256) void gemm64x2(
    const float* __restrict__ A, const float* __restrict__ B, float* __restrict__ C,
    int K, int lda, int ldb, int ldc)
{
    __shared__ float As[16][68];
    __shared__ float Bs[16][64];
    const int tid = threadIdx.x;
    const int tx = tid & 15, ty = tid >> 4;
    const int rowbase = blockIdx.y * 64;
    const int colbase = blockIdx.x * 64;
    unsigned long long acc[4][2] = {};
    for (int k0 = 0; k0 < K; k0 += 16) {
        {
            int m = tid >> 2, k = (tid & 3) * 4;
            float4 v = *reinterpret_cast<const float4*>(A + (size_t)(rowbase + m) * lda + k0 + k);
            As[k + 0][m] = v.x; As[k + 1][m] = v.y; As[k + 2][m] = v.z; As[k + 3][m] = v.w;
        }
        {
            int k = tid >> 4, n = (tid & 15) * 4;
            *reinterpret_cast<float4*>(&Bs[k][n]) =
                *reinterpret_cast<const float4*>(B + (size_t)(k0 + k) * ldb + colbase + n);
        }
        __syncthreads();
        #pragma unroll
        for (int kk = 0; kk < 16; kk++) {
            float4 a4 = *reinterpret_cast<const float4*>(&As[kk][ty * 4]);
            ulonglong2 b2 = *reinterpret_cast<const ulonglong2*>(&Bs[kk][tx * 4]);
            unsigned long long a0 = pack2(a4.x, a4.x), a1 = pack2(a4.y, a4.y);
            unsigned long long a2 = pack2(a4.z, a4.z), a3 = pack2(a4.w, a4.w);
            acc[0][0] = f32x2_fma(a0, b2.x, acc[0][0]); acc[0][1] = f32x2_fma(a0, b2.y, acc[0][1]);
            acc[1][0] = f32x2_fma(a1, b2.x, acc[1][0]); acc[1][1] = f32x2_fma(a1, b2.y, acc[1][1]);
            acc[2][0] = f32x2_fma(a2, b2.x, acc[2][0]); acc[2][1] = f32x2_fma(a2, b2.y, acc[2][1]);
            acc[3][0] = f32x2_fma(a3, b2.x, acc[3][0]); acc[3][1] = f32x2_fma(a3, b2.y, acc[3][1]);
        }
        __syncthreads();
    }
    #pragma unroll
    for (int i = 0; i < 4; i++) {
        float2 p0 = unpack2(acc[i][0]), p1 = unpack2(acc[i][1]);
        *reinterpret_cast<float4*>(C + (size_t)(rowbase + ty * 4 + i) * ldc + colbase + tx * 4) =
            make_float4(p0.x, p0.y, p1.x, p1.y);
    }
}

// ============================================================
// Fused prep: zero mv+rowsum, hi/lo split of x, transpose+split w.
// ============================================================
#define PREP_ZMV   512
#define PREP_ZRS   (PREP_ZMV + 64)
#define PREP_X     (PREP_ZRS + 4096)
#define PREP_W     (PREP_X + 136)

__global__ __launch_bounds__(256) void prep_kernel(
    const float* __restrict__ X, const float* __restrict__ W,
    float* __restrict__ mv, float* __restrict__ rowsum,
    __nv_bfloat16* __restrict__ Xh, __nv_bfloat16* __restrict__ Xl,
    __nv_bfloat16* __restrict__ Wh, __nv_bfloat16* __restrict__ Wl)
{
    __shared__ float s[64][65];
    const int blk = blockIdx.x;
    const int tid = threadIdx.x;

    if (blk < PREP_ZMV) {
        reinterpret_cast<float4*>(mv)[blk * 256 + tid] = make_float4(0.f, 0.f, 0.f, 0.f);
    } else if (blk < PREP_ZRS) {
        reinterpret_cast<float4*>(rowsum)[(blk - PREP_ZMV) * 256 + tid] =
            make_float4(0.f, 0.f, 0.f, 0.f);
    } else if (blk < PREP_X) {
        int idx = (blk - PREP_ZRS) * 256 + tid;
        float4 v = reinterpret_cast<const float4*>(X)[idx];
        size_t o = (size_t)idx * 4;
        __nv_bfloat16 h0 = __float2bfloat16_rn(v.x), h1 = __float2bfloat16_rn(v.y);
        __nv_bfloat16 h2 = __float2bfloat16_rn(v.z), h3 = __float2bfloat16_rn(v.w);
        Xh[o+0]=h0; Xh[o+1]=h1; Xh[o+2]=h2; Xh[o+3]=h3;
        Xl[o+0]=__float2bfloat16_rn(v.x - __bfloat162float(h0));
        Xl[o+1]=__float2bfloat16_rn(v.y - __bfloat162float(h1));
        Xl[o+2]=__float2bfloat16_rn(v.z - __bfloat162float(h2));
        Xl[o+3]=__float2bfloat16_rn(v.w - __bfloat162float(h3));
    } else {
        int tile = blk - PREP_X;
        int n0 = (tile % 17) * 64, k0 = (tile / 17) * 64;
        #pragma unroll
        for (int e = tid; e < 64 * 64; e += 256) {
            int r = e >> 6, c = e & 63;
            s[r][c] = W[(size_t)(k0 + r) * QKVN + n0 + c];
        }
        __syncthreads();
        #pragma unroll
        for (int e = tid; e < 64 * 64; e += 256) {
            int r = e >> 6, c = e & 63;
            float v = s[c][r];
            __nv_bfloat16 h = __float2bfloat16_rn(v);
            Wh[(size_t)(n0 + r) * HID + k0 + c] = h;
            Wl[(size_t)(n0 + r) * HID + k0 + c] = __float2bfloat16_rn(v - __bfloat162float(h));
        }
    }
}

// ============================================================
// qkv GEMM on HMMA; epilogue writes Q,K directly as bf16 hi/lo
// in [b][h][t][d] layout, V as fp32 into g_v.
// ============================================================
#define GB_STRIDE 40

__global__ __launch_bounds__(256) void gemm_bf16_kernel(
    const __nv_bfloat16* __restrict__ Ah, const __nv_bfloat16* __restrict__ Al,
    const __nv_bfloat16* __restrict__ BhT, const __nv_bfloat16* __restrict__ BlT,
    __nv_bfloat16* __restrict__ Qh, __nv_bfloat16* __restrict__ Ql,
    __nv_bfloat16* __restrict__ Kh, __nv_bfloat16* __restrict__ Kl,
    float* __restrict__ V)
{
    __shared__ __nv_bfloat16 sAh[128][GB_STRIDE];
    __shared__ __nv_bfloat16 sAl[128][GB_STRIDE];
    __shared__ __nv_bfloat16 sBh[64][GB_STRIDE];
    __shared__ __nv_bfloat16 sBl[64][GB_STRIDE];

    const int tid = threadIdx.x;
    const int wid = tid >> 5, lane = tid & 31;
    const int rowbase = blockIdx.y * 128;
    const int colbase = blockIdx.x * 64;
    const int mbase = (wid & 3) * 32, nbase = (wid >> 2) * 32;
    const int lr = lane >> 2, lk = (lane & 3) * 2;

    float acc[2][4][4];
    #pragma unroll
    for (int i = 0; i < 2; i++)
        #pragma unroll
        for (int j = 0; j < 4; j++)
            #pragma unroll
            for (int t = 0; t < 4; t++) acc[i][j][t] = 0.f;

    for (int k0 = 0; k0 < HID; k0 += 32) {
        #pragma unroll
        for (int e = tid; e < 512; e += 256) {
            int r = e >> 2, c = (e & 3) * 8;
            *(uint4*)(&sAh[r][c]) = *(const uint4*)(Ah + (size_t)(rowbase + r) * HID + k0 + c);
            *(uint4*)(&sAl[r][c]) = *(const uint4*)(Al + (size_t)(rowbase + r) * HID + k0 + c);
        }
        {
            int r = tid >> 2, c = (tid & 3) * 8;
            *(uint4*)(&sBh[r][c]) = *(const uint4*)(BhT + (size_t)(colbase + r) * HID + k0 + c);
            *(uint4*)(&sBl[r][c]) = *(const uint4*)(BlT + (size_t)(colbase + r) * HID + k0 + c);
        }
        __syncthreads();
        #pragma unroll
        for (int ks = 0; ks < 2; ks++) {
            const int kb = ks * 16 + lk;
            uint32_t ah[2][4], al[2][4];
            #pragma unroll
            for (int i = 0; i < 2; i++) {
                int r0 = mbase + i * 16 + lr;
                ah[i][0] = *(const uint32_t*)(&sAh[r0][kb]);
                ah[i][1] = *(const uint32_t*)(&sAh[r0 + 8][kb]);
                ah[i][2] = *(const uint32_t*)(&sAh[r0][kb + 8]);
                ah[i][3] = *(const uint32_t*)(&sAh[r0 + 8][kb + 8]);
                al[i][0] = *(const uint32_t*)(&sAl[r0][kb]);
                al[i][1] = *(const uint32_t*)(&sAl[r0 + 8][kb]);
                al[i][2] = *(const uint32_t*)(&sAl[r0][kb + 8]);
                al[i][3] = *(const uint32_t*)(&sAl[r0 + 8][kb + 8]);
            }
            #pragma unroll
            for (int j = 0; j < 4; j++) {
                int n = nbase + j * 8 + lr;
                uint32_t bh0 = *(const uint32_t*)(&sBh[n][kb]);
                uint32_t bh1 = *(const uint32_t*)(&sBh[n][kb + 8]);
                uint32_t bl0 = *(const uint32_t*)(&sBl[n][kb]);
                uint32_t bl1 = *(const uint32_t*)(&sBl[n][kb + 8]);
                #pragma unroll
                for (int i = 0; i < 2; i++) {
                    mma16816(acc[i][j][0], acc[i][j][1], acc[i][j][2], acc[i][j][3],
                             ah[i][0], ah[i][1], ah[i][2], ah[i][3], bh0, bh1);
                    mma16816(acc[i][j][0], acc[i][j][1], acc[i][j][2], acc[i][j][3],
                             ah[i][0], ah[i][1], ah[i][2], ah[i][3], bl0, bl1);
                    mma16816(acc[i][j][0], acc[i][j][1], acc[i][j][2], acc[i][j][3],
                             al[i][0], al[i][1], al[i][2], al[i][3], bh0, bh1);
                }
            }
        }
        __syncthreads();
    }

    #pragma unroll
    for (int i = 0; i < 2; i++) {
        int r = rowbase + mbase + i * 16 + lr;
        int b = r >> 11, t = r & (T - 1);
        #pragma unroll
        for (int j = 0; j < 4; j++) {
            int col = colbase + nbase + j * 8 + lk;
            float v0 = acc[i][j][0], v1 = acc[i][j][1];
            float v2 = acc[i][j][2], v3 = acc[i][j][3];
            if (col < 1024) {
                int hh = (col >> 6) & 7;
                int d  = col & 63;
                __nv_bfloat16* oh = (col >= 512) ? Kh : Qh;
                __nv_bfloat16* ol = (col >= 512) ? Kl : Ql;
                size_t dst  = ((size_t)(b * NH + hh) * T + t) * DH + d;
                size_t dst8 = dst + 8 * DH;
                uint32_t h01 = bf2pair(v0, v1);
                uint32_t h23 = bf2pair(v2, v3);
                __nv_bfloat162 hp0 = *reinterpret_cast<__nv_bfloat162*>(&h01);
                __nv_bfloat162 hp2 = *reinterpret_cast<__nv_bfloat162*>(&h23);
                uint32_t l01 = bf2pair(v0 - __bfloat162float(hp0.x),
                                       v1 - __bfloat162float(hp0.y));
                uint32_t l23 = bf2pair(v2 - __bfloat162float(hp2.x),
                                       v3 - __bfloat162float(hp2.y));
                *reinterpret_cast<uint32_t*>(oh + dst)  = h01;
                *reinterpret_cast<uint32_t*>(ol + dst)  = l01;
                *reinterpret_cast<uint32_t*>(oh + dst8) = h23;
                *reinterpret_cast<uint32_t*>(ol + dst8) = l23;
            } else {
                int d = col - 1024;
                size_t dst = ((size_t)b * T + t) * DH + d;
                *reinterpret_cast<float2*>(V + dst)          = make_float2(v0, v1);
                *reinterpret_cast<float2*>(V + dst + 8 * DH) = make_float2(v2, v3);
            }
        }
    }
}

// ============================================================
// Score passes. Column-split warp tiles, LDSM fragment loads.
// ============================================================
#define SC_STRIDE 72
#define SC_SMEM   (4 * 128 * SC_STRIDE * 2)

__device__ __forceinline__ void scores_load_tiles(
    const __nv_bfloat16* __restrict__ Qh, const __nv_bfloat16* __restrict__ Ql,
    const __nv_bfloat16* __restrict__ Kh, const __nv_bfloat16* __restrict__ Kl,
    int ki, int qi, int bh, __nv_bfloat16* smem)
{
    __nv_bfloat16* sQh = smem;
    __nv_bfloat16* sQl = smem + 128 * SC_STRIDE;
    __nv_bfloat16* sKh = smem + 2 * 128 * SC_STRIDE;
    __nv_bfloat16* sKl = smem + 3 * 128 * SC_STRIDE;
    const int tid = threadIdx.x;
    const size_t qoff = ((size_t)bh * T + qi * 128) * DH;
    const size_t koff = ((size_t)bh * T + ki * 128) * DH;
    #pragma unroll
    for (int e = tid; e < 1024; e += 256) {
        int r = e >> 3, c = (e & 7) * 8;
        *(uint4*)(sQh + r * SC_STRIDE + c) = *(const uint4*)(Qh + qoff + r * DH + c);
        *(uint4*)(sQl + r * SC_STRIDE + c) = *(const uint4*)(Ql + qoff + r * DH + c);
        *(uint4*)(sKh + r * SC_STRIDE + c) = *(const uint4*)(Kh + koff + r * DH + c);
        *(uint4*)(sKl + r * SC_STRIDE + c) = *(const uint4*)(Kl + koff + r * DH + c);
    }
    __syncthreads();
}

// One 32(q) x 32(k) half per warp; fragments via ldmatrix.x4.
__device__ __forceinline__ void scores_half_mma(
    const __nv_bfloat16* smem, int c2, float acc[2][4][4])
{
    const __nv_bfloat16* sQh = smem;
    const __nv_bfloat16* sQl = smem + 128 * SC_STRIDE;
    const __nv_bfloat16* sKh = smem + 2 * 128 * SC_STRIDE;
    const __nv_bfloat16* sKl = smem + 3 * 128 * SC_STRIDE;

    const int tid = threadIdx.x;
    const int wid = tid >> 5, lane = tid & 31;
    const int wr = wid & 3, wc = wid >> 2;

    const int a_row = lane & 15;
    const int a_col = (lane >> 4) << 3;
    const int b_row = ((lane >> 4) << 3) + (lane & 7);
    const int b_col = ((lane >> 3) & 1) << 3;

    #pragma unroll
    for (int i = 0; i < 2; i++)
        #pragma unroll
        for (int j = 0; j < 4; j++)
            #pragma unroll
            for (int t = 0; t < 4; t++) acc[i][j][t] = 0.f;

    #pragma unroll
    for (int ks = 0; ks < 4; ks++) {
        const int kb0 = ks * 16;
        uint32_t ah[2][4], al[2][4];
        #pragma unroll
        for (int i = 0; i < 2; i++) {
            int r0 = wr * 32 + i * 16 + a_row;
            ldsm_x4(ah[i][0], ah[i][1], ah[i][2], ah[i][3],
                    smem_addr_u32(sQh + r0 * SC_STRIDE + kb0 + a_col));
            ldsm_x4(al[i][0], al[i][1], al[i][2], al[i][3],
                    smem_addr_u32(sQl + r0 * SC_STRIDE + kb0 + a_col));
        }
        #pragma unroll
        for (int jj = 0; jj < 2; jj++) {
            int n0 = wc * 64 + c2 * 32 + jj * 16 + b_row;
            uint32_t bh[4], bl[4];
            ldsm_x4(bh[0], bh[1], bh[2], bh[3],
                    smem_addr_u32(sKh + n0 * SC_STRIDE + kb0 + b_col));
            ldsm_x4(bl[0], bl[1], bl[2], bl[3],
                    smem_addr_u32(sKl + n0 * SC_STRIDE + kb0 + b_col));
            #pragma unroll
            for (int dj = 0; dj < 2; dj++) {
                int j = jj * 2 + dj;
                #pragma unroll
                for (int i = 0; i < 2; i++) {
                    mma16816(acc[i][j][0], acc[i][j][1], acc[i][j][2], acc[i][j][3],
                             ah[i][0], ah[i][1], ah[i][2], ah[i][3],
                             bh[2*dj], bh[2*dj+1]);
                    mma16816(acc[i][j][0], acc[i][j][1], acc[i][j][2], acc[i][j][3],
                             ah[i][0], ah[i][1], ah[i][2], ah[i][3],
                             bl[2*dj], bl[2*dj+1]);
                    mma16816(acc[i][j][0], acc[i][j][1], acc[i][j][2], acc[i][j][3],
                             al[i][0], al[i][1], al[i][2], al[i][3],
                             bh[2*dj], bh[2*dj+1]);
                }
            }
        }
    }
}

// Pass 1: rowsums; upper-tri blocks zero-fill P; interior tiles unmasked.
__global__ __launch_bounds__(256, 3) void scores_sum_kernel(
    const __nv_bfloat16* __restrict__ Qh, const __nv_bfloat16* __restrict__ Ql,
    const __nv_bfloat16* __restrict__ Kh, const __nv_bfloat16* __restrict__ Kl,
    float* __restrict__ rowsum, float* __restrict__ P)
{
    const int ki = blockIdx.x, qi = blockIdx.y, bh = blockIdx.z;
    const int tid = threadIdx.x;

    if (ki > qi) {
        const size_t base = ((size_t)bh * T + qi * 128) * T + ki * 128;
        const float4 z = make_float4(0.f, 0.f, 0.f, 0.f);
        #pragma unroll
        for (int e = tid; e < 4096; e += 256) {
            int r = e >> 5, c4 = (e & 31) * 4;
            *reinterpret_cast<float4*>(&P[base + (size_t)r * T + c4]) = z;
        }
        return;
    }
    const bool diag = (ki == qi);

    extern __shared__ __nv_bfloat16 smem[];
    scores_load_tiles(Qh, Ql, Kh, Kl, ki, qi, bh, smem);

    const int wid = tid >> 5, lane = tid & 31;
    const int wr = wid & 3, wc = wid >> 2;
    const int lr = lane >> 2, lk = (lane & 3) * 2;
    const float scale = 0.125f;

    float rs0a = 0.f, rs1a = 0.f, rs0b = 0.f, rs1b = 0.f;
    #pragma unroll
    for (int c2 = 0; c2 < 2; c2++) {
        float acc[2][4][4];
        scores_half_mma(smem, c2, acc);
        #pragma unroll
        for (int i = 0; i < 2; i++) {
            float rs0 = 0.f, rs1 = 0.f;
            if (diag) {
                int q0 = qi * 128 + wr * 32 + i * 16 + lr;
                int q1 = q0 + 8;
                #pragma unroll
                for (int j = 0; j < 4; j++) {
                    int col = ki * 128 + wc * 64 + c2 * 32 + j * 8 + lk;
                    if (col     <= q0) rs0 += __expf(acc[i][j][0] * scale);
                    if (col + 1 <= q0) rs0 += __expf(acc[i][j][1] * scale);
                    if (col     <= q1) rs1 += __expf(acc[i][j][2] * scale);
                    if (col + 1 <= q1) rs1 += __expf(acc[i][j][3] * scale);
                }
            } else {
                #pragma unroll
                for (int j = 0; j < 4; j++) {
                    rs0 += __expf(acc[i][j][0] * scale) + __expf(acc[i][j][1] * scale);
                    rs1 += __expf(acc[i][j][2] * scale) + __expf(acc[i][j][3] * scale);
                }
            }
            if (i == 0) { rs0a += rs0; rs1a += rs1; }
            else        { rs0b += rs0; rs1b += rs1; }
        }
    }
    #pragma unroll
    for (int o = 1; o <= 2; o <<= 1) {
        rs0a += __shfl_xor_sync(0xffffffffu, rs0a, o);
        rs1a += __shfl_xor_sync(0xffffffffu, rs1a, o);
        rs0b += __shfl_xor_sync(0xffffffffu, rs0b, o);
        rs1b += __shfl_xor_sync(0xffffffffu, rs1b, o);
    }
    if ((lane & 3) == 0) {
        int q0 = qi * 128 + wr * 32 + lr;
        atomicAdd(&rowsum[(size_t)bh * T + q0], rs0a);
        atomicAdd(&rowsum[(size_t)bh * T + q0 + 8], rs1a);
        atomicAdd(&rowsum[(size_t)bh * T + q0 + 16], rs0b);
        atomicAdd(&rowsum[(size_t)bh * T + q0 + 24], rs1b);
    }
}

// Pass 2: recompute, normalize, write final P; interior tiles unmasked.
__global__ __launch_bounds__(256, 3) void scores_norm_kernel(
    const __nv_bfloat16* __restrict__ Qh, const __nv_bfloat16* __restrict__ Ql,
    const __nv_bfloat16* __restrict__ Kh, const __nv_bfloat16* __restrict__ Kl,
    const float* __restrict__ rowsum, float* __restrict__ P)
{
    const int ki = blockIdx.x, qi = blockIdx.y, bh = blockIdx.z;
    if (ki > qi) return;
    const bool diag = (ki == qi);
    const int tid = threadIdx.x;

    extern __shared__ __nv_bfloat16 smem[];
    scores_load_tiles(Qh, Ql, Kh, Kl, ki, qi, bh, smem);

    const int wid = tid >> 5, lane = tid & 31;
    const int wr = wid & 3, wc = wid >> 2;
    const int lr = lane >> 2, lk = (lane & 3) * 2;
    const float scale = 0.125f;

    const int q0 = qi * 128 + wr * 32 + lr;
    const float inv0 = 1.0f / rowsum[(size_t)bh * T + q0];
    const float inv1 = 1.0f / rowsum[(size_t)bh * T + q0 + 8];
    const float inv2 = 1.0f / rowsum[(size_t)bh * T + q0 + 16];
    const float inv3 = 1.0f / rowsum[(size_t)bh * T + q0 + 24];

    #pragma unroll
    for (int c2 = 0; c2 < 2; c2++) {
        float acc[2][4][4];
        scores_half_mma(smem, c2, acc);
        #pragma unroll
        for (int i = 0; i < 2; i++) {
            int qa = q0 + i * 16;
            int qb = qa + 8;
            float iva = (i == 0) ? inv0 : inv2;
            float ivb = (i == 0) ? inv1 : inv3;
            if (diag) {
                #pragma unroll
                for (int j = 0; j < 4; j++) {
                    int col = ki * 128 + wc * 64 + c2 * 32 + j * 8 + lk;
                    {
                        size_t o = ((size_t)bh * T + qa) * T + col;
                        float2 v;
                        v.x = (col     > qa) ? 0.f : __expf(acc[i][j][0] * scale) * iva;
                        v.y = (col + 1 > qa) ? 0.f : __expf(acc[i][j][1] * scale) * iva;
                        *reinterpret_cast<float2*>(&P[o]) = v;
                    }
                    {
                        size_t o = ((size_t)bh * T + qb) * T + col;
                        float2 v;
                        v.x = (col     > qb) ? 0.f : __expf(acc[i][j][2] * scale) * ivb;
                        v.y = (col + 1 > qb) ? 0.f : __expf(acc[i][j][3] * scale) * ivb;
                        *reinterpret_cast<float2*>(&P[o]) = v;
                    }
                }
            } else {
                #pragma unroll
                for (int j = 0; j < 4; j++) {
                    int col = ki * 128 + wc * 64 + c2 * 32 + j * 8 + lk;
                    {
                        size_t o = ((size_t)bh * T + qa) * T + col;
                        float2 v;
                        v.x = __expf(acc[i][j][0] * scale) * iva;
                        v.y = __expf(acc[i][j][1] * scale) * iva;
                        *reinterpret_cast<float2*>(&P[o]) = v;
                    }
                    {
                        size_t o = ((size_t)bh * T + qb) * T + col;
                        float2 v;
                        v.x = __expf(acc[i][j][2] * scale) * ivb;
                        v.y = __expf(acc[i][j][3] * scale) * ivb;
                        *reinterpret_cast<float2*>(&P[o]) = v;
                    }
                }
            }
        }
    }
}

// ============================================================
// mv += (1/8) * sum_{heads in group} P @ V over strips of up to
// 4 kt tiles. grid (8, 32, BS*2): z = b*2 + hg, heads hg*4..hg*4+3.
// Doubled concurrency vs single-group version.
// ============================================================
__global__ __launch_bounds__(256) void pv_strip_kernel(
    const float* __restrict__ P, const float* __restrict__ V,
    float* __restrict__ mv)
{
    const int s = blockIdx.x, qt = blockIdx.y;
    const int b = blockIdx.z >> 1, hg = blockIdx.z & 1;
    const int kt0 = s * 4;
    if (kt0 > qt) return;
    const int kt1 = (qt < kt0 + 3) ? qt : (kt0 + 3);

    __shared__ float Ps[64][65];
    __shared__ float Vs[64][64];

    const int tid = threadIdx.x;
    const int tx = tid & 15, ty = tid >> 4;
    const float* Vbase = V + (size_t)b * T * DH;
    const float* Pbase = P + (size_t)(b * NH + hg * 4) * T * T;

    unsigned long long acc[4][2] = {};

    for (int kt = kt0; kt <= kt1; kt++) {
        #pragma unroll
        for (int e = tid; e < 64 * 16; e += 256) {
            int r = e >> 4, c4 = (e & 15) * 4;
            *reinterpret_cast<float4*>(&Vs[r][c4]) =
                *reinterpret_cast<const float4*>(Vbase + (size_t)(kt * 64 + r) * DH + c4);
            const size_t off = ((size_t)(qt * 64 + r)) * T + kt * 64 + c4;
            float4 sv = make_float4(0.f, 0.f, 0.f, 0.f);
            #pragma unroll
            for (int h = 0; h < 4; h++) {
                float4 v = *reinterpret_cast<const float4*>(
                    Pbase + (size_t)h * T * T + off);
                sv.x += v.x; sv.y += v.y; sv.z += v.z; sv.w += v.w;
            }
            Ps[r][c4 + 0] = sv.x * 0.125f; Ps[r][c4 + 1] = sv.y * 0.125f;
            Ps[r][c4 + 2] = sv.z * 0.125f; Ps[r][c4 + 3] = sv.w * 0.125f;
        }
        __syncthreads();

        #pragma unroll 16
        for (int kk = 0; kk < 64; kk++) {
            ulonglong2 b2 = *reinterpret_cast<const ulonglong2*>(&Vs[kk][tx * 4]);
            #pragma unroll
            for (int i = 0; i < 4; i++) {
                float a = Ps[ty * 4 + i][kk];
                unsigned long long a2 = pack2(a, a);
                acc[i][0] = f32x2_fma(a2, b2.x, acc[i][0]);
                acc[i][1] = f32x2_fma(a2, b2.y, acc[i][1]);
            }
        }
        __syncthreads();
    }

    #pragma unroll
    for (int i = 0; i < 4; i++) {
        float* dst = &mv[((size_t)b * T + qt * 64 + ty * 4 + i) * DH + tx * 4];
        float2 p0 = unpack2(acc[i][0]), p1 = unpack2(acc[i][1]);
        atomicAdd(dst + 0, p0.x);
        atomicAdd(dst + 1, p0.y);
        atomicAdd(dst + 2, p1.x);
        atomicAdd(dst + 3, p1.y);
    }
}

// ============================================================
extern "C" void kernel_launch(void* const* d_in, const int* in_sizes, int n_in,
                              void* d_out, int out_size)
{
    const float* x     = (const float*)d_in[0];
    const float* w_qkv = (const float*)d_in[1];
    const float* w_out = (const float*)d_in[2];

    const long OUT_E  = (long)ROWS * HID;
    const long PROB_E = (long)BS * NH * T * T;

    float *v_p, *mv_p, *rowsum_p, *probs_fb, *out_fb;
    __nv_bfloat16 *qh_p, *ql_p, *kh_p, *kl_p, *xh_p, *xl_p, *wh_p, *wl_p;
    cudaGetSymbolAddress((void**)&v_p,      g_v);
    cudaGetSymbolAddress((void**)&mv_p,     g_mv);
    cudaGetSymbolAddress((void**)&rowsum_p, g_rowsum);
    cudaGetSymbolAddress((void**)&qh_p,     g_qh);
    cudaGetSymbolAddress((void**)&ql_p,     g_ql);
    cudaGetSymbolAddress((void**)&kh_p,     g_kh);
    cudaGetSymbolAddress((void**)&kl_p,     g_kl);
    cudaGetSymbolAddress((void**)&xh_p,     g_xh);
    cudaGetSymbolAddress((void**)&xl_p,     g_xl);
    cudaGetSymbolAddress((void**)&wh_p,     g_wh);
    cudaGetSymbolAddress((void**)&wl_p,     g_wl);
    cudaGetSymbolAddress((void**)&probs_fb, g_probs_fallback);
    cudaGetSymbolAddress((void**)&out_fb,   g_out_fallback);

    float* out_ptr;
    float* probs_ptr;
    if ((long)out_size >= OUT_E + PROB_E) {
        out_ptr   = (float*)d_out;
        probs_ptr = (float*)d_out + OUT_E;
    } else if ((long)out_size == PROB_E) {
        out_ptr   = out_fb;
        probs_ptr = (float*)d_out;
    } else {
        out_ptr   = (float*)d_out;
        probs_ptr = probs_fb;
    }

    cudaFuncSetAttribute(scores_sum_kernel,
                         cudaFuncAttributeMaxDynamicSharedMemorySize, SC_SMEM);
    cudaFuncSetAttribute(scores_norm_kernel,
                         cudaFuncAttributeMaxDynamicSharedMemorySize, SC_SMEM);

    // 1) fused prep
    prep_kernel<<<PREP_W, 256>>>(x, w_qkv, mv_p, rowsum_p, xh_p, xl_p, wh_p, wl_p);

    // 2) qkv GEMM; epilogue emits Q,K bf16 hi/lo + V fp32
    gemm_bf16_kernel<<<dim3(QKVN / 64, ROWS / 128), 256>>>(
        xh_p, xl_p, wh_p, wl_p, qh_p, ql_p, kh_p, kl_p, v_p);

    // 3) pass 1: rowsums + upper-tri zero-fill of P
    scores_sum_kernel<<<dim3(T / 128, T / 128, BS * NH), 256, SC_SMEM>>>(
        qh_p, ql_p, kh_p, kl_p, rowsum_p, probs_ptr);

    // 4) pass 2: normalized probs (lower-tri only)
    scores_norm_kernel<<<dim3(T / 128, T / 128, BS * NH), 256, SC_SMEM>>>(
        qh_p, ql_p, kh_p, kl_p, rowsum_p, probs_ptr);

    // 5) mv = mean_h(P) @ V (4-tile strips, head-split across 2 blocks)
    pv_strip_kernel<<<dim3(8, T / 64, BS * 2), 256>>>(probs_ptr, v_p, mv_p);

    // 6) out = mv @ w_out
    gemm64x2<<<dim3(HID / 64, ROWS / 64), 256>>>(mv_p, w_out, out_ptr, DH, DH, HID, HID);
}

// round 17
// speedup vs baseline: 1.1400x; 1.0470x over previous
#include <cuda_runtime.h>
#include <cuda_bf16.h>
#include <math.h>
#include <stdint.h>

#define BS   4
#define T    2048
#define HID  512
#define NH   8
#define DH   64
#define QKVN ((2*NH+1)*DH)   // 1088
#define ROWS (BS*T)          // 8192

// ---- scratch ----
__device__ float g_v  [(size_t)ROWS * DH];
__device__ float g_mv [(size_t)ROWS * DH];
__device__ float g_rowsum[(size_t)BS * NH * T];
__device__ __nv_bfloat16 g_qh[(size_t)BS * NH * T * DH];
__device__ __nv_bfloat16 g_ql[(size_t)BS * NH * T * DH];
__device__ __nv_bfloat16 g_kh[(size_t)BS * NH * T * DH];
__device__ __nv_bfloat16 g_kl[(size_t)BS * NH * T * DH];
__device__ __nv_bfloat16 g_xh[(size_t)ROWS * HID];
__device__ __nv_bfloat16 g_xl[(size_t)ROWS * HID];
__device__ __nv_bfloat16 g_wh[(size_t)QKVN * HID];
__device__ __nv_bfloat16 g_wl[(size_t)QKVN * HID];
__device__ float g_probs_fallback[(size_t)BS * NH * T * T];
__device__ float g_out_fallback[(size_t)ROWS * HID];

// ---- packed f32x2 helpers ----
__device__ __forceinline__ unsigned long long f32x2_fma(
    unsigned long long a, unsigned long long b, unsigned long long c) {
    unsigned long long d;
    asm("fma.rn.f32x2 %0, %1, %2, %3;" : "=l"(d) : "l"(a), "l"(b), "l"(c));
    return d;
}
__device__ __forceinline__ unsigned long long pack2(float lo, float hi) {
    unsigned long long r;
    asm("mov.b64 %0, {%1, %2};" : "=l"(r) : "f"(lo), "f"(hi));
    return r;
}
__device__ __forceinline__ float2 unpack2(unsigned long long v) {
    float2 r;
    asm("mov.b64 {%0, %1}, %2;" : "=f"(r.x), "=f"(r.y) : "l"(v));
    return r;
}

// ---- warp mma bf16 m16n8k16, fp32 accum ----
__device__ __forceinline__ void mma16816(
    float& c0, float& c1, float& c2, float& c3,
    uint32_t a0, uint32_t a1, uint32_t a2, uint32_t a3,
    uint32_t b0, uint32_t b1)
{
    asm volatile(
        "mma.sync.aligned.m16n8k16.row.col.f32.bf16.bf16.f32 "
        "{%0,%1,%2,%3}, {%4,%5,%6,%7}, {%8,%9}, {%0,%1,%2,%3};"
        : "+f"(c0), "+f"(c1), "+f"(c2), "+f"(c3)
        : "r"(a0), "r"(a1), "r"(a2), "r"(a3), "r"(b0), "r"(b1));
}

__device__ __forceinline__ void ldsm_x4(
    uint32_t& r0, uint32_t& r1, uint32_t& r2, uint32_t& r3, uint32_t addr)
{
    asm volatile("ldmatrix.sync.aligned.m8n8.x4.shared.b16 {%0,%1,%2,%3}, [%4];"
                 : "=r"(r0), "=r"(r1), "=r"(r2), "=r"(r3) : "r"(addr));
}
__device__ __forceinline__ uint32_t smem_addr_u32(const void* p) {
    return (uint32_t)__cvta_generic_to_shared(p);
}

__device__ __forceinline__ uint32_t bf2pair(float a, float b) {
    __nv_bfloat162 p;
    p.x = __float2bfloat16_rn(a);
    p.y = __float2bfloat16_rn(b);
    return *reinterpret_cast<uint32_t*>(&p);
}

// ============================================================
// Small fp32 GEMM (out = mv @ w_out, K=64).
// ============================================================
__global__ __launch_bounds__(256) void gemm64x2(
    const float* __restrict__ A, const float* __restrict__ B, float* __restrict__ C,
    int K, int lda, int ldb, int ldc)
{
    __shared__ float As[16][68];
    __shared__ float Bs[16][64];
    const int tid = threadIdx.x;
    const int tx = tid & 15, ty = tid >> 4;
    const int rowbase = blockIdx.y * 64;
    const int colbase = blockIdx.x * 64;
    unsigned long long acc[4][2] = {};
    for (int k0 = 0; k0 < K; k0 += 16) {
        {
            int m = tid >> 2, k = (tid & 3) * 4;
            float4 v = *reinterpret_cast<const float4*>(A + (size_t)(rowbase + m) * lda + k0 + k);
            As[k + 0][m] = v.x; As[k + 1][m] = v.y; As[k + 2][m] = v.z; As[k + 3][m] = v.w;
        }
        {
            int k = tid >> 4, n = (tid & 15) * 4;
            *reinterpret_cast<float4*>(&Bs[k][n]) =
                *reinterpret_cast<const float4*>(B + (size_t)(k0 + k) * ldb + colbase + n);
        }
        __syncthreads();
        #pragma unroll
        for (int kk = 0; kk < 16; kk++) {
            float4 a4 = *reinterpret_cast<const float4*>(&As[kk][ty * 4]);
            ulonglong2 b2 = *reinterpret_cast<const ulonglong2*>(&Bs[kk][tx * 4]);
            unsigned long long a0 = pack2(a4.x, a4.x), a1 = pack2(a4.y, a4.y);
            unsigned long long a2 = pack2(a4.z, a4.z), a3 = pack2(a4.w, a4.w);
            acc[0][0] = f32x2_fma(a0, b2.x, acc[0][0]); acc[0][1] = f32x2_fma(a0, b2.y, acc[0][1]);
            acc[1][0] = f32x2_fma(a1, b2.x, acc[1][0]); acc[1][1] = f32x2_fma(a1, b2.y, acc[1][1]);
            acc[2][0] = f32x2_fma(a2, b2.x, acc[2][0]); acc[2][1] = f32x2_fma(a2, b2.y, acc[2][1]);
            acc[3][0] = f32x2_fma(a3, b2.x, acc[3][0]); acc[3][1] = f32x2_fma(a3, b2.y, acc[3][1]);
        }
        __syncthreads();
    }
    #pragma unroll
    for (int i = 0; i < 4; i++) {
        float2 p0 = unpack2(acc[i][0]), p1 = unpack2(acc[i][1]);
        *reinterpret_cast<float4*>(C + (size_t)(rowbase + ty * 4 + i) * ldc + colbase + tx * 4) =
            make_float4(p0.x, p0.y, p1.x, p1.y);
    }
}

// ============================================================
// Fused prep: zero mv+rowsum, hi/lo split of x, transpose+split w.
// ============================================================
#define PREP_ZMV   512
#define PREP_ZRS   (PREP_ZMV + 64)
#define PREP_X     (PREP_ZRS + 4096)
#define PREP_W     (PREP_X + 136)

__global__ __launch_bounds__(256) void prep_kernel(
    const float* __restrict__ X, const float* __restrict__ W,
    float* __restrict__ mv, float* __restrict__ rowsum,
    __nv_bfloat16* __restrict__ Xh, __nv_bfloat16* __restrict__ Xl,
    __nv_bfloat16* __restrict__ Wh, __nv_bfloat16* __restrict__ Wl)
{
    __shared__ float s[64][65];
    const int blk = blockIdx.x;
    const int tid = threadIdx.x;

    if (blk < PREP_ZMV) {
        reinterpret_cast<float4*>(mv)[blk * 256 + tid] = make_float4(0.f, 0.f, 0.f, 0.f);
    } else if (blk < PREP_ZRS) {
        reinterpret_cast<float4*>(rowsum)[(blk - PREP_ZMV) * 256 + tid] =
            make_float4(0.f, 0.f, 0.f, 0.f);
    } else if (blk < PREP_X) {
        int idx = (blk - PREP_ZRS) * 256 + tid;
        float4 v = reinterpret_cast<const float4*>(X)[idx];
        size_t o = (size_t)idx * 4;
        __nv_bfloat16 h0 = __float2bfloat16_rn(v.x), h1 = __float2bfloat16_rn(v.y);
        __nv_bfloat16 h2 = __float2bfloat16_rn(v.z), h3 = __float2bfloat16_rn(v.w);
        Xh[o+0]=h0; Xh[o+1]=h1; Xh[o+2]=h2; Xh[o+3]=h3;
        Xl[o+0]=__float2bfloat16_rn(v.x - __bfloat162float(h0));
        Xl[o+1]=__float2bfloat16_rn(v.y - __bfloat162float(h1));
        Xl[o+2]=__float2bfloat16_rn(v.z - __bfloat162float(h2));
        Xl[o+3]=__float2bfloat16_rn(v.w - __bfloat162float(h3));
    } else {
        int tile = blk - PREP_X;
        int n0 = (tile % 17) * 64, k0 = (tile / 17) * 64;
        #pragma unroll
        for (int e = tid; e < 64 * 64; e += 256) {
            int r = e >> 6, c = e & 63;
            s[r][c] = W[(size_t)(k0 + r) * QKVN + n0 + c];
        }
        __syncthreads();
        #pragma unroll
        for (int e = tid; e < 64 * 64; e += 256) {
            int r = e >> 6, c = e & 63;
            float v = s[c][r];
            __nv_bfloat16 h = __float2bfloat16_rn(v);
            Wh[(size_t)(n0 + r) * HID + k0 + c] = h;
            Wl[(size_t)(n0 + r) * HID + k0 + c] = __float2bfloat16_rn(v - __bfloat162float(h));
        }
    }
}

// ============================================================
// qkv GEMM on HMMA; epilogue writes Q,K directly as bf16 hi/lo
// in [b][h][t][d] layout, V as fp32 into g_v.
// ============================================================
#define GB_STRIDE 40

__global__ __launch_bounds__(256) void gemm_bf16_kernel(
    const __nv_bfloat16* __restrict__ Ah, const __nv_bfloat16* __restrict__ Al,
    const __nv_bfloat16* __restrict__ BhT, const __nv_bfloat16* __restrict__ BlT,
    __nv_bfloat16* __restrict__ Qh, __nv_bfloat16* __restrict__ Ql,
    __nv_bfloat16* __restrict__ Kh, __nv_bfloat16* __restrict__ Kl,
    float* __restrict__ V)
{
    __shared__ __nv_bfloat16 sAh[128][GB_STRIDE];
    __shared__ __nv_bfloat16 sAl[128][GB_STRIDE];
    __shared__ __nv_bfloat16 sBh[64][GB_STRIDE];
    __shared__ __nv_bfloat16 sBl[64][GB_STRIDE];

    const int tid = threadIdx.x;
    const int wid = tid >> 5, lane = tid & 31;
    const int rowbase = blockIdx.y * 128;
    const int colbase = blockIdx.x * 64;
    const int mbase = (wid & 3) * 32, nbase = (wid >> 2) * 32;
    const int lr = lane >> 2, lk = (lane & 3) * 2;

    float acc[2][4][4];
    #pragma unroll
    for (int i = 0; i < 2; i++)
        #pragma unroll
        for (int j = 0; j < 4; j++)
            #pragma unroll
            for (int t = 0; t < 4; t++) acc[i][j][t] = 0.f;

    for (int k0 = 0; k0 < HID; k0 += 32) {
        #pragma unroll
        for (int e = tid; e < 512; e += 256) {
            int r = e >> 2, c = (e & 3) * 8;
            *(uint4*)(&sAh[r][c]) = *(const uint4*)(Ah + (size_t)(rowbase + r) * HID + k0 + c);
            *(uint4*)(&sAl[r][c]) = *(const uint4*)(Al + (size_t)(rowbase + r) * HID + k0 + c);
        }
        {
            int r = tid >> 2, c = (tid & 3) * 8;
            *(uint4*)(&sBh[r][c]) = *(const uint4*)(BhT + (size_t)(colbase + r) * HID + k0 + c);
            *(uint4*)(&sBl[r][c]) = *(const uint4*)(BlT + (size_t)(colbase + r) * HID + k0 + c);
        }
        __syncthreads();
        #pragma unroll
        for (int ks = 0; ks < 2; ks++) {
            const int kb = ks * 16 + lk;
            uint32_t ah[2][4], al[2][4];
            #pragma unroll
            for (int i = 0; i < 2; i++) {
                int r0 = mbase + i * 16 + lr;
                ah[i][0] = *(const uint32_t*)(&sAh[r0][kb]);
                ah[i][1] = *(const uint32_t*)(&sAh[r0 + 8][kb]);
                ah[i][2] = *(const uint32_t*)(&sAh[r0][kb + 8]);
                ah[i][3] = *(const uint32_t*)(&sAh[r0 + 8][kb + 8]);
                al[i][0] = *(const uint32_t*)(&sAl[r0][kb]);
                al[i][1] = *(const uint32_t*)(&sAl[r0 + 8][kb]);
                al[i][2] = *(const uint32_t*)(&sAl[r0][kb + 8]);
                al[i][3] = *(const uint32_t*)(&sAl[r0 + 8][kb + 8]);
            }
            #pragma unroll
            for (int j = 0; j < 4; j++) {
                int n = nbase + j * 8 + lr;
                uint32_t bh0 = *(const uint32_t*)(&sBh[n][kb]);
                uint32_t bh1 = *(const uint32_t*)(&sBh[n][kb + 8]);
                uint32_t bl0 = *(const uint32_t*)(&sBl[n][kb]);
                uint32_t bl1 = *(const uint32_t*)(&sBl[n][kb + 8]);
                #pragma unroll
                for (int i = 0; i < 2; i++) {
                    mma16816(acc[i][j][0], acc[i][j][1], acc[i][j][2], acc[i][j][3],
                             ah[i][0], ah[i][1], ah[i][2], ah[i][3], bh0, bh1);
                    mma16816(acc[i][j][0], acc[i][j][1], acc[i][j][2], acc[i][j][3],
                             ah[i][0], ah[i][1], ah[i][2], ah[i][3], bl0, bl1);
                    mma16816(acc[i][j][0], acc[i][j][1], acc[i][j][2], acc[i][j][3],
                             al[i][0], al[i][1], al[i][2], al[i][3], bh0, bh1);
                }
            }
        }
        __syncthreads();
    }

    #pragma unroll
    for (int i = 0; i < 2; i++) {
        int r = rowbase + mbase + i * 16 + lr;
        int b = r >> 11, t = r & (T - 1);
        #pragma unroll
        for (int j = 0; j < 4; j++) {
            int col = colbase + nbase + j * 8 + lk;
            float v0 = acc[i][j][0], v1 = acc[i][j][1];
            float v2 = acc[i][j][2], v3 = acc[i][j][3];
            if (col < 1024) {
                int hh = (col >> 6) & 7;
                int d  = col & 63;
                __nv_bfloat16* oh = (col >= 512) ? Kh : Qh;
                __nv_bfloat16* ol = (col >= 512) ? Kl : Ql;
                size_t dst  = ((size_t)(b * NH + hh) * T + t) * DH + d;
                size_t dst8 = dst + 8 * DH;
                uint32_t h01 = bf2pair(v0, v1);
                uint32_t h23 = bf2pair(v2, v3);
                __nv_bfloat162 hp0 = *reinterpret_cast<__nv_bfloat162*>(&h01);
                __nv_bfloat162 hp2 = *reinterpret_cast<__nv_bfloat162*>(&h23);
                uint32_t l01 = bf2pair(v0 - __bfloat162float(hp0.x),
                                       v1 - __bfloat162float(hp0.y));
                uint32_t l23 = bf2pair(v2 - __bfloat162float(hp2.x),
                                       v3 - __bfloat162float(hp2.y));
                *reinterpret_cast<uint32_t*>(oh + dst)  = h01;
                *reinterpret_cast<uint32_t*>(ol + dst)  = l01;
                *reinterpret_cast<uint32_t*>(oh + dst8) = h23;
                *reinterpret_cast<uint32_t*>(ol + dst8) = l23;
            } else {
                int d = col - 1024;
                size_t dst = ((size_t)b * T + t) * DH + d;
                *reinterpret_cast<float2*>(V + dst)          = make_float2(v0, v1);
                *reinterpret_cast<float2*>(V + dst + 8 * DH) = make_float2(v2, v3);
            }
        }
    }
}

// ============================================================
// Single score pass: MMA + exp + diag mask; stores UNNORMALIZED
// exp-P; rowsum atomics; upper-tri zero-fill.
// ============================================================
#define SC_STRIDE 72
#define SC_SMEM   (4 * 128 * SC_STRIDE * 2)

__device__ __forceinline__ void scores_load_tiles(
    const __nv_bfloat16* __restrict__ Qh, const __nv_bfloat16* __restrict__ Ql,
    const __nv_bfloat16* __restrict__ Kh, const __nv_bfloat16* __restrict__ Kl,
    int ki, int qi, int bh, __nv_bfloat16* smem)
{
    __nv_bfloat16* sQh = smem;
    __nv_bfloat16* sQl = smem + 128 * SC_STRIDE;
    __nv_bfloat16* sKh = smem + 2 * 128 * SC_STRIDE;
    __nv_bfloat16* sKl = smem + 3 * 128 * SC_STRIDE;
    const int tid = threadIdx.x;
    const size_t qoff = ((size_t)bh * T + qi * 128) * DH;
    const size_t koff = ((size_t)bh * T + ki * 128) * DH;
    #pragma unroll
    for (int e = tid; e < 1024; e += 256) {
        int r = e >> 3, c = (e & 7) * 8;
        *(uint4*)(sQh + r * SC_STRIDE + c) = *(const uint4*)(Qh + qoff + r * DH + c);
        *(uint4*)(sQl + r * SC_STRIDE + c) = *(const uint4*)(Ql + qoff + r * DH + c);
        *(uint4*)(sKh + r * SC_STRIDE + c) = *(const uint4*)(Kh + koff + r * DH + c);
        *(uint4*)(sKl + r * SC_STRIDE + c) = *(const uint4*)(Kl + koff + r * DH + c);
    }
    __syncthreads();
}

__device__ __forceinline__ void scores_half_mma(
    const __nv_bfloat16* smem, int c2, float acc[2][4][4])
{
    const __nv_bfloat16* sQh = smem;
    const __nv_bfloat16* sQl = smem + 128 * SC_STRIDE;
    const __nv_bfloat16* sKh = smem + 2 * 128 * SC_STRIDE;
    const __nv_bfloat16* sKl = smem + 3 * 128 * SC_STRIDE;

    const int tid = threadIdx.x;
    const int wid = tid >> 5, lane = tid & 31;
    const int wr = wid & 3, wc = wid >> 2;

    const int a_row = lane & 15;
    const int a_col = (lane >> 4) << 3;
    const int b_row = ((lane >> 4) << 3) + (lane & 7);
    const int b_col = ((lane >> 3) & 1) << 3;

    #pragma unroll
    for (int i = 0; i < 2; i++)
        #pragma unroll
        for (int j = 0; j < 4; j++)
            #pragma unroll
            for (int t = 0; t < 4; t++) acc[i][j][t] = 0.f;

    #pragma unroll
    for (int ks = 0; ks < 4; ks++) {
        const int kb0 = ks * 16;
        uint32_t ah[2][4], al[2][4];
        #pragma unroll
        for (int i = 0; i < 2; i++) {
            int r0 = wr * 32 + i * 16 + a_row;
            ldsm_x4(ah[i][0], ah[i][1], ah[i][2], ah[i][3],
                    smem_addr_u32(sQh + r0 * SC_STRIDE + kb0 + a_col));
            ldsm_x4(al[i][0], al[i][1], al[i][2], al[i][3],
                    smem_addr_u32(sQl + r0 * SC_STRIDE + kb0 + a_col));
        }
        #pragma unroll
        for (int jj = 0; jj < 2; jj++) {
            int n0 = wc * 64 + c2 * 32 + jj * 16 + b_row;
            uint32_t bh[4], bl[4];
            ldsm_x4(bh[0], bh[1], bh[2], bh[3],
                    smem_addr_u32(sKh + n0 * SC_STRIDE + kb0 + b_col));
            ldsm_x4(bl[0], bl[1], bl[2], bl[3],
                    smem_addr_u32(sKl + n0 * SC_STRIDE + kb0 + b_col));
            #pragma unroll
            for (int dj = 0; dj < 2; dj++) {
                int j = jj * 2 + dj;
                #pragma unroll
                for (int i = 0; i < 2; i++) {
                    mma16816(acc[i][j][0], acc[i][j][1], acc[i][j][2], acc[i][j][3],
                             ah[i][0], ah[i][1], ah[i][2], ah[i][3],
                             bh[2*dj], bh[2*dj+1]);
                    mma16816(acc[i][j][0], acc[i][j][1], acc[i][j][2], acc[i][j][3],
                             ah[i][0], ah[i][1], ah[i][2], ah[i][3],
                             bl[2*dj], bl[2*dj+1]);
                    mma16816(acc[i][j][0], acc[i][j][1], acc[i][j][2], acc[i][j][3],
                             al[i][0], al[i][1], al[i][2], al[i][3],
                             bh[2*dj], bh[2*dj+1]);
                }
            }
        }
    }
}

__global__ __launch_bounds__(256, 3) void scores_exp_kernel(
    const __nv_bfloat16* __restrict__ Qh, const __nv_bfloat16* __restrict__ Ql,
    const __nv_bfloat16* __restrict__ Kh, const __nv_bfloat16* __restrict__ Kl,
    float* __restrict__ rowsum, float* __restrict__ P)
{
    const int ki = blockIdx.x, qi = blockIdx.y, bh = blockIdx.z;
    const int tid = threadIdx.x;

    if (ki > qi) {
        const size_t base = ((size_t)bh * T + qi * 128) * T + ki * 128;
        const float4 z = make_float4(0.f, 0.f, 0.f, 0.f);
        #pragma unroll
        for (int e = tid; e < 4096; e += 256) {
            int r = e >> 5, c4 = (e & 31) * 4;
            *reinterpret_cast<float4*>(&P[base + (size_t)r * T + c4]) = z;
        }
        return;
    }
    const bool diag = (ki == qi);

    extern __shared__ __nv_bfloat16 smem[];
    scores_load_tiles(Qh, Ql, Kh, Kl, ki, qi, bh, smem);

    const int wid = tid >> 5, lane = tid & 31;
    const int wr = wid & 3, wc = wid >> 2;
    const int lr = lane >> 2, lk = (lane & 3) * 2;
    const float scale = 0.125f;

    float rs0a = 0.f, rs1a = 0.f, rs0b = 0.f, rs1b = 0.f;
    #pragma unroll
    for (int c2 = 0; c2 < 2; c2++) {
        float acc[2][4][4];
        scores_half_mma(smem, c2, acc);
        #pragma unroll
        for (int i = 0; i < 2; i++) {
            int qa = qi * 128 + wr * 32 + i * 16 + lr;
            int qb = qa + 8;
            float rs0 = 0.f, rs1 = 0.f;
            #pragma unroll
            for (int j = 0; j < 4; j++) {
                int col = ki * 128 + wc * 64 + c2 * 32 + j * 8 + lk;
                float2 va, vb;
                if (diag) {
                    va.x = (col     > qa) ? 0.f : __expf(acc[i][j][0] * scale);
                    va.y = (col + 1 > qa) ? 0.f : __expf(acc[i][j][1] * scale);
                    vb.x = (col     > qb) ? 0.f : __expf(acc[i][j][2] * scale);
                    vb.y = (col + 1 > qb) ? 0.f : __expf(acc[i][j][3] * scale);
                } else {
                    va.x = __expf(acc[i][j][0] * scale);
                    va.y = __expf(acc[i][j][1] * scale);
                    vb.x = __expf(acc[i][j][2] * scale);
                    vb.y = __expf(acc[i][j][3] * scale);
                }
                rs0 += va.x + va.y;
                rs1 += vb.x + vb.y;
                *reinterpret_cast<float2*>(&P[((size_t)bh * T + qa) * T + col]) = va;
                *reinterpret_cast<float2*>(&P[((size_t)bh * T + qb) * T + col]) = vb;
            }
            if (i == 0) { rs0a += rs0; rs1a += rs1; }
            else        { rs0b += rs0; rs1b += rs1; }
        }
    }
    #pragma unroll
    for (int o = 1; o <= 2; o <<= 1) {
        rs0a += __shfl_xor_sync(0xffffffffu, rs0a, o);
        rs1a += __shfl_xor_sync(0xffffffffu, rs1a, o);
        rs0b += __shfl_xor_sync(0xffffffffu, rs0b, o);
        rs1b += __shfl_xor_sync(0xffffffffu, rs1b, o);
    }
    if ((lane & 3) == 0) {
        int q0 = qi * 128 + wr * 32 + lr;
        atomicAdd(&rowsum[(size_t)bh * T + q0], rs0a);
        atomicAdd(&rowsum[(size_t)bh * T + q0 + 8], rs1a);
        atomicAdd(&rowsum[(size_t)bh * T + q0 + 16], rs0b);
        atomicAdd(&rowsum[(size_t)bh * T + q0 + 24], rs1b);
    }
}

// ============================================================
// pv + in-place normalize: for each lower-tri tile (qt, kt),
// read unnormalized exp-P for all 8 heads, multiply by inv,
// write normalized P back, accumulate head-mean, matmul with V.
// grid (8, 32, BS), 4-tile strips (R14 layout).
// ============================================================
__global__ __launch_bounds__(256) void pv_norm_kernel(
    float* __restrict__ P, const float* __restrict__ V,
    const float* __restrict__ rowsum, float* __restrict__ mv)
{
    const int s = blockIdx.x, qt = blockIdx.y, b = blockIdx.z;
    const int kt0 = s * 4;
    if (kt0 > qt) return;
    const int kt1 = (qt < kt0 + 3) ? qt : (kt0 + 3);

    __shared__ float Ps[64][65];
    __shared__ float Vs[64][64];
    __shared__ float invs[NH][64];

    const int tid = threadIdx.x;
    const int tx = tid & 15, ty = tid >> 4;
    const float* Vbase = V + (size_t)b * T * DH;

    // per-row inverse sums for this qt, all 8 heads
    for (int e = tid; e < NH * 64; e += 256) {
        int h = e >> 6, r = e & 63;
        invs[h][r] = 1.0f / rowsum[(size_t)(b * NH + h) * T + qt * 64 + r];
    }
    __syncthreads();

    unsigned long long acc[4][2] = {};

    for (int kt = kt0; kt <= kt1; kt++) {
        #pragma unroll
        for (int e = tid; e < 64 * 16; e += 256) {
            int r = e >> 4, c4 = (e & 15) * 4;
            *reinterpret_cast<float4*>(&Vs[r][c4]) =
                *reinterpret_cast<const float4*>(Vbase + (size_t)(kt * 64 + r) * DH + c4);
            const size_t off = ((size_t)(qt * 64 + r)) * T + kt * 64 + c4;
            float4 sv = make_float4(0.f, 0.f, 0.f, 0.f);
            #pragma unroll
            for (int h = 0; h < NH; h++) {
                float* ptr = P + (size_t)(b * NH + h) * T * T + off;
                float4 v = *reinterpret_cast<const float4*>(ptr);
                float iv = invs[h][r];
                v.x *= iv; v.y *= iv; v.z *= iv; v.w *= iv;
                *reinterpret_cast<float4*>(ptr) = v;      // normalized P out
                sv.x += v.x; sv.y += v.y; sv.z += v.z; sv.w += v.w;
            }
            Ps[r][c4 + 0] = sv.x * 0.125f; Ps[r][c4 + 1] = sv.y * 0.125f;
            Ps[r][c4 + 2] = sv.z * 0.125f; Ps[r][c4 + 3] = sv.w * 0.125f;
        }
        __syncthreads();

        #pragma unroll 16
        for (int kk = 0; kk < 64; kk++) {
            ulonglong2 b2 = *reinterpret_cast<const ulonglong2*>(&Vs[kk][tx * 4]);
            #pragma unroll
            for (int i = 0; i < 4; i++) {
                float a = Ps[ty * 4 + i][kk];
                unsigned long long a2 = pack2(a, a);
                acc[i][0] = f32x2_fma(a2, b2.x, acc[i][0]);
                acc[i][1] = f32x2_fma(a2, b2.y, acc[i][1]);
            }
        }
        __syncthreads();
    }

    #pragma unroll
    for (int i = 0; i < 4; i++) {
        float* dst = &mv[((size_t)b * T + qt * 64 + ty * 4 + i) * DH + tx * 4];
        float2 p0 = unpack2(acc[i][0]), p1 = unpack2(acc[i][1]);
        atomicAdd(dst + 0, p0.x);
        atomicAdd(dst + 1, p0.y);
        atomicAdd(dst + 2, p1.x);
        atomicAdd(dst + 3, p1.y);
    }
}

// ============================================================
extern "C" void kernel_launch(void* const* d_in, const int* in_sizes, int n_in,
                              void* d_out, int out_size)
{
    const float* x     = (const float*)d_in[0];
    const float* w_qkv = (const float*)d_in[1];
    const float* w_out = (const float*)d_in[2];

    const long OUT_E  = (long)ROWS * HID;
    const long PROB_E = (long)BS * NH * T * T;

    float *v_p, *mv_p, *rowsum_p, *probs_fb, *out_fb;
    __nv_bfloat16 *qh_p, *ql_p, *kh_p, *kl_p, *xh_p, *xl_p, *wh_p, *wl_p;
    cudaGetSymbolAddress((void**)&v_p,      g_v);
    cudaGetSymbolAddress((void**)&mv_p,     g_mv);
    cudaGetSymbolAddress((void**)&rowsum_p, g_rowsum);
    cudaGetSymbolAddress((void**)&qh_p,     g_qh);
    cudaGetSymbolAddress((void**)&ql_p,     g_ql);
    cudaGetSymbolAddress((void**)&kh_p,     g_kh);
    cudaGetSymbolAddress((void**)&kl_p,     g_kl);
    cudaGetSymbolAddress((void**)&xh_p,     g_xh);
    cudaGetSymbolAddress((void**)&xl_p,     g_xl);
    cudaGetSymbolAddress((void**)&wh_p,     g_wh);
    cudaGetSymbolAddress((void**)&wl_p,     g_wl);
    cudaGetSymbolAddress((void**)&probs_fb, g_probs_fallback);
    cudaGetSymbolAddress((void**)&out_fb,   g_out_fallback);

    float* out_ptr;
    float* probs_ptr;
    if ((long)out_size >= OUT_E + PROB_E) {
        out_ptr   = (float*)d_out;
        probs_ptr = (float*)d_out + OUT_E;
    } else if ((long)out_size == PROB_E) {
        out_ptr   = out_fb;
        probs_ptr = (float*)d_out;
    } else {
        out_ptr   = (float*)d_out;
        probs_ptr = probs_fb;
    }

    cudaFuncSetAttribute(scores_exp_kernel,
                         cudaFuncAttributeMaxDynamicSharedMemorySize, SC_SMEM);

    // 1) fused prep (zeros mv + rowsum, x/w hi-lo splits)
    prep_kernel<<<PREP_W, 256>>>(x, w_qkv, mv_p, rowsum_p, xh_p, xl_p, wh_p, wl_p);

    // 2) qkv GEMM; epilogue emits Q,K bf16 hi/lo + V fp32
    gemm_bf16_kernel<<<dim3(QKVN / 64, ROWS / 128), 256>>>(
        xh_p, xl_p, wh_p, wl_p, qh_p, ql_p, kh_p, kl_p, v_p);

    // 3) single score pass: unnormalized exp-P + rowsums + zero-fill
    scores_exp_kernel<<<dim3(T / 128, T / 128, BS * NH), 256, SC_SMEM>>>(
        qh_p, ql_p, kh_p, kl_p, rowsum_p, probs_ptr);

    // 4) pv: normalize P in place + head-mean + @ V
    pv_norm_kernel<<<dim3(8, T / 64, BS), 256>>>(probs_ptr, v_p, rowsum_p, mv_p);

    // 5) out = mv @ w_out
    gemm64x2<<<dim3(HID / 64, ROWS / 64), 256>>>(mv_p, w_out, out_ptr, DH, DH, HID, HID);
}